// round 6
// baseline (speedup 1.0000x reference)
#include <cuda_runtime.h>
#include <cuda_bf16.h>
#include <cuda_fp16.h>
#include <cstdint>

// Problem constants
#define BB 8
#define SS 1024
#define DD 512
#define HH 8
#define HD 64
#define FF 2048
#define NROWS (BB*SS)          // 8192
#define L2E 1.4426950408889634f

// ---------------- helpers ----------------------------------------------------
__device__ __forceinline__ uint32_t smem_to_u32(const void* p) {
    uint32_t a;
    asm("{ .reg .u64 t; cvta.to.shared.u64 t, %1; cvt.u32.u64 %0, t; }"
        : "=r"(a) : "l"(p));
    return a;
}
__device__ __forceinline__ void cpasync16(uint32_t s, const void* g) {
    asm volatile("cp.async.cg.shared.global [%0], [%1], 16;" :: "r"(s), "l"(g));
}
__device__ __forceinline__ void cpasync_commit() {
    asm volatile("cp.async.commit_group;" ::: "memory");
}
__device__ __forceinline__ void cpasync_wait1() {
    asm volatile("cp.async.wait_group 1;" ::: "memory");
}
__device__ __forceinline__ void ldsm4(uint32_t* r, uint32_t addr) {
    asm volatile("ldmatrix.sync.aligned.m8n8.x4.shared.b16 {%0,%1,%2,%3}, [%4];"
        : "=r"(r[0]), "=r"(r[1]), "=r"(r[2]), "=r"(r[3]) : "r"(addr));
}
__device__ __forceinline__ void ldsm4t(uint32_t* r, uint32_t addr) {
    asm volatile("ldmatrix.sync.aligned.m8n8.x4.trans.shared.b16 {%0,%1,%2,%3}, [%4];"
        : "=r"(r[0]), "=r"(r[1]), "=r"(r[2]), "=r"(r[3]) : "r"(addr));
}
__device__ __forceinline__ void mma16816(float* c, const uint32_t* a, const uint32_t* b) {
    asm volatile(
        "mma.sync.aligned.m16n8k16.row.col.f32.bf16.bf16.f32 "
        "{%0,%1,%2,%3}, {%4,%5,%6,%7}, {%8,%9}, {%0,%1,%2,%3};"
        : "+f"(c[0]), "+f"(c[1]), "+f"(c[2]), "+f"(c[3])
        : "r"(a[0]), "r"(a[1]), "r"(a[2]), "r"(a[3]), "r"(b[0]), "r"(b[1]));
}
__device__ __forceinline__ void mma16816h(float* c, const uint32_t* a, const uint32_t* b) {
    asm volatile(
        "mma.sync.aligned.m16n8k16.row.col.f32.f16.f16.f32 "
        "{%0,%1,%2,%3}, {%4,%5,%6,%7}, {%8,%9}, {%0,%1,%2,%3};"
        : "+f"(c[0]), "+f"(c[1]), "+f"(c[2]), "+f"(c[3])
        : "r"(a[0]), "r"(a[1]), "r"(a[2]), "r"(a[3]), "r"(b[0]), "r"(b[1]));
}
__device__ __forceinline__ void split_bf16(float v, __nv_bfloat16& h, __nv_bfloat16& l) {
    h = __float2bfloat16_rn(v);
    l = __float2bfloat16_rn(v - __bfloat162float(h));
}
__device__ __forceinline__ void split_f16(float v, __half& h, __half& l) {
    h = __float2half_rn(v);
    l = __float2half_rn(v - __half2float(h));
}
__device__ __forceinline__ uint32_t packh(float x0, float x1) {
    uint32_t r;
    asm("cvt.rn.f16x2.f32 %0, %1, %2;" : "=r"(r) : "f"(x1), "f"(x0));
    return r;
}
__device__ __forceinline__ uint32_t ex2h2(uint32_t v) {
    uint32_t r;
    asm("ex2.approx.f16x2 %0, %1;" : "=r"(r) : "r"(v));
    return r;
}
__device__ __forceinline__ float ex2f(float x) {
    float r;
    asm("ex2.approx.f32 %0, %1;" : "=f"(r) : "f"(x));
    return r;
}

// ---------------- scratch (device globals) ----------------------------------
__device__ __nv_bfloat16 g_hhi [NROWS*DD], g_hlo [NROWS*DD];
__device__ __nv_bfloat16 g_qhi [NROWS*DD], g_qlo [NROWS*DD];
__device__ __nv_bfloat16 g_khi [NROWS*DD], g_klo [NROWS*DD];
__device__ __half        g_vhi [NROWS*DD], g_vlo [NROWS*DD];
__device__ __nv_bfloat16 g_chi [NROWS*DD], g_clo [NROWS*DD];
__device__ float         g_x2  [NROWS*DD];
__device__ __nv_bfloat16 g_h2hi[NROWS*DD], g_h2lo[NROWS*DD];
__device__ __nv_bfloat16 g_fhi [NROWS*FF], g_flo [NROWS*FF];
__device__ __nv_bfloat16 g_wqhi[DD*DD], g_wqlo[DD*DD];
__device__ __nv_bfloat16 g_wkhi[DD*DD], g_wklo[DD*DD];
__device__ __nv_bfloat16 g_wvhi[DD*DD], g_wvlo[DD*DD];
__device__ __nv_bfloat16 g_wohi[DD*DD], g_wolo[DD*DD];
__device__ __nv_bfloat16 g_w1hi[FF*DD], g_w1lo[FF*DD];
__device__ __nv_bfloat16 g_w2hi[DD*FF], g_w2lo[DD*FF];

// ---------------- fused fp32 -> (hi, lo) conversion for 6 weights ------------
struct CvtArgs {
    const float* s[6];
    __nv_bfloat16* h[6];
    __nv_bfloat16* l[6];
    int n4[6];
};
__global__ __launch_bounds__(256) void cvt6_kernel(CvtArgs a)
{
    int w = blockIdx.y;
    int i = blockIdx.x * 256 + threadIdx.x;
    if (i >= a.n4[w]) return;
    float4 v = ((const float4*)a.s[w])[i];
    __nv_bfloat16 h[4], l[4];
    split_bf16(v.x, h[0], l[0]); split_bf16(v.y, h[1], l[1]);
    split_bf16(v.z, h[2], l[2]); split_bf16(v.w, h[3], l[3]);
    *(uint2*)(a.h[w] + (size_t)i * 4) = *(uint2*)h;
    *(uint2*)(a.l[w] + (size_t)i * 4) = *(uint2*)l;
}

// ---------------- RMSNorm: writes hi/lo bf16 ---------------------------------
__global__ __launch_bounds__(256) void rmsnorm_kernel(
    const float* __restrict__ x, const float* __restrict__ w,
    __nv_bfloat16* __restrict__ ohi, __nv_bfloat16* __restrict__ olo)
{
    int row = blockIdx.x;
    const float* xr = x + (size_t)row * DD;
    int t = threadIdx.x;
    float v0 = xr[t];
    float v1 = xr[t + 256];
    float ss = v0 * v0 + v1 * v1;
    #pragma unroll
    for (int off = 16; off; off >>= 1)
        ss += __shfl_xor_sync(0xffffffffu, ss, off);
    __shared__ float red[8];
    if ((t & 31) == 0) red[t >> 5] = ss;
    __syncthreads();
    float total = 0.f;
    #pragma unroll
    for (int i = 0; i < 8; i++) total += red[i];
    float inv = rsqrtf(total * (1.0f / DD) + 1e-6f);
    float o0 = w[t] * v0 * inv;
    float o1 = w[t + 256] * v1 * inv;
    __nv_bfloat16 h, l;
    size_t base = (size_t)row * DD;
    split_bf16(o0, h, l); ohi[base + t] = h;       olo[base + t] = l;
    split_bf16(o1, h, l); ohi[base + t + 256] = h; olo[base + t + 256] = l;
}

// ---------------- split-bf16 tensor-core GEMM (mma.sync) ---------------------
// C[M,N] = epi( A[M,K] @ B[N,K]^T (+R) ), A/B given as bf16 hi/lo pairs.
// EPI: 1 = relu -> bf16 hi/lo   2 = +R -> fp32   3 = bf16 hi/lo
//      4 = f16 hi/lo            5 = *log2e -> bf16 hi/lo
// 128x128 CTA tile, K-chunk 64, 3-stage cp.async pipeline, MMAs grouped by term.
#define STG 65536
#define OFF_ALO 16384
#define OFF_BHI 32768
#define OFF_BLO 49152
#define TSWZ(r, c16) ((uint32_t)((r) * 128 + (((c16) ^ ((r) & 7)) << 4)))

template <int EPI>
__global__ __launch_bounds__(256) void gemm_mma_kernel(
    const __nv_bfloat16* __restrict__ Ahi, const __nv_bfloat16* __restrict__ Alo,
    const __nv_bfloat16* __restrict__ Bhi, const __nv_bfloat16* __restrict__ Blo,
    const float* __restrict__ R, float* __restrict__ Cf,
    __nv_bfloat16* __restrict__ Chi, __nv_bfloat16* __restrict__ Clo,
    int N, int K)
{
    extern __shared__ char smem[];
    uint32_t sb = smem_to_u32(smem);
    int tid = threadIdx.x;
    int wid = tid >> 5, lane = tid & 31;
    int bm = blockIdx.y * 128, bn = blockIdx.x * 128;

    int lr0 = tid >> 3, lc = tid & 7;
    uint32_t soff[4];
    uint32_t ofsA[4], ofsB[4];
    #pragma unroll
    for (int it = 0; it < 4; it++) {
        int r = lr0 + it * 32;
        soff[it] = TSWZ(r, lc);
        ofsA[it] = (uint32_t)((bm + r) * K + lc * 8);
        ofsB[it] = (uint32_t)((bn + r) * K + lc * 8);
    }

    #define ISSUE(s, kt) do {                                                   \
        uint32_t _b = sb + (uint32_t)(s) * STG;                                 \
        uint32_t _ko = (uint32_t)(kt) * 64;                                     \
        _Pragma("unroll")                                                       \
        for (int _it = 0; _it < 4; _it++) {                                     \
            cpasync16(_b + soff[_it],           Ahi + ofsA[_it] + _ko);         \
            cpasync16(_b + OFF_ALO + soff[_it], Alo + ofsA[_it] + _ko);         \
            cpasync16(_b + OFF_BHI + soff[_it], Bhi + ofsB[_it] + _ko);         \
            cpasync16(_b + OFF_BLO + soff[_it], Blo + ofsB[_it] + _ko);         \
        }                                                                       \
        cpasync_commit();                                                       \
    } while (0)

    float acc[2][8][4];
    #pragma unroll
    for (int ma = 0; ma < 2; ma++)
        #pragma unroll
        for (int na = 0; na < 8; na++)
            #pragma unroll
            for (int j = 0; j < 4; j++) acc[ma][na][j] = 0.f;

    int wm = wid & 3, wn = wid >> 2;
    int arow = wm * 32 + (lane & 15);
    int ac16 = lane >> 4;
    int brow = wn * 64 + (lane & 7) + ((lane >> 4) & 1) * 8;
    int bc16 = (lane >> 3) & 1;

    const int NC = K >> 6;
    ISSUE(0, 0);
    ISSUE(1, 1);

    int stg = 0;                // stage of current chunk
    #pragma unroll 1
    for (int kt = 0; kt < NC; kt++) {
        cpasync_wait1();
        __syncthreads();
        if (kt + 2 < NC) {
            int ns = stg + 2; if (ns >= 3) ns -= 3;
            ISSUE(ns, kt + 2);
        }

        uint32_t ab = sb + (uint32_t)stg * STG;
        #pragma unroll
        for (int kk = 0; kk < 4; kk++) {
            uint32_t ah[2][4], al[2][4];
            #pragma unroll
            for (int ma = 0; ma < 2; ma++) {
                uint32_t ad = ab + TSWZ(arow + ma * 16, ac16 + kk * 2);
                ldsm4(ah[ma], ad);
                ldsm4(al[ma], ad + OFF_ALO);
            }
            uint32_t bh[4][4], bl[4][4];
            #pragma unroll
            for (int np = 0; np < 4; np++) {
                uint32_t bd = ab + OFF_BHI + TSWZ(brow + np * 16, bc16 + kk * 2);
                ldsm4(bh[np], bd);
                ldsm4(bl[np], bd + 16384);
            }
            // term hh (16 independent MMAs)
            #pragma unroll
            for (int np = 0; np < 4; np++)
                #pragma unroll
                for (int ma = 0; ma < 2; ma++) {
                    mma16816(acc[ma][np*2],   ah[ma], bh[np]);
                    mma16816(acc[ma][np*2+1], ah[ma], bh[np] + 2);
                }
            // term hl
            #pragma unroll
            for (int np = 0; np < 4; np++)
                #pragma unroll
                for (int ma = 0; ma < 2; ma++) {
                    mma16816(acc[ma][np*2],   ah[ma], bl[np]);
                    mma16816(acc[ma][np*2+1], ah[ma], bl[np] + 2);
                }
            // term lh
            #pragma unroll
            for (int np = 0; np < 4; np++)
                #pragma unroll
                for (int ma = 0; ma < 2; ma++) {
                    mma16816(acc[ma][np*2],   al[ma], bh[np]);
                    mma16816(acc[ma][np*2+1], al[ma], bh[np] + 2);
                }
        }
        if (++stg >= 3) stg = 0;
    }

    // epilogue
    int g = lane >> 2, tg = lane & 3;
    #pragma unroll
    for (int ma = 0; ma < 2; ma++) {
        #pragma unroll
        for (int na = 0; na < 8; na++) {
            int row = bm + wm * 32 + ma * 16 + g;
            int col = bn + wn * 64 + na * 8 + tg * 2;
            float* c = acc[ma][na];
            size_t o0 = (size_t)row * N + col;
            size_t o1 = (size_t)(row + 8) * N + col;
            if (EPI == 1 || EPI == 3 || EPI == 5) {
                float v0 = c[0], v1 = c[1], v2 = c[2], v3 = c[3];
                if (EPI == 1) {
                    v0 = fmaxf(v0, 0.f); v1 = fmaxf(v1, 0.f);
                    v2 = fmaxf(v2, 0.f); v3 = fmaxf(v3, 0.f);
                }
                if (EPI == 5) { v0 *= L2E; v1 *= L2E; v2 *= L2E; v3 *= L2E; }
                __nv_bfloat16 h0[2], l0[2], h1[2], l1[2];
                split_bf16(v0, h0[0], l0[0]); split_bf16(v1, h0[1], l0[1]);
                split_bf16(v2, h1[0], l1[0]); split_bf16(v3, h1[1], l1[1]);
                *(uint32_t*)(Chi + o0) = *(uint32_t*)h0;
                *(uint32_t*)(Clo + o0) = *(uint32_t*)l0;
                *(uint32_t*)(Chi + o1) = *(uint32_t*)h1;
                *(uint32_t*)(Clo + o1) = *(uint32_t*)l1;
            } else if (EPI == 4) {
                __half* Hh = (__half*)Chi;
                __half* Hl = (__half*)Clo;
                __half h0[2], l0[2], h1[2], l1[2];
                split_f16(c[0], h0[0], l0[0]); split_f16(c[1], h0[1], l0[1]);
                split_f16(c[2], h1[0], l1[0]); split_f16(c[3], h1[1], l1[1]);
                *(uint32_t*)(Hh + o0) = *(uint32_t*)h0;
                *(uint32_t*)(Hl + o0) = *(uint32_t*)l0;
                *(uint32_t*)(Hh + o1) = *(uint32_t*)h1;
                *(uint32_t*)(Hl + o1) = *(uint32_t*)l1;
            } else {
                float2 v0 = make_float2(c[0], c[1]);
                float2 v1 = make_float2(c[2], c[3]);
                if (EPI == 2) {
                    float2 r0 = *(const float2*)(R + o0);
                    float2 r1 = *(const float2*)(R + o1);
                    v0.x += r0.x; v0.y += r0.y;
                    v1.x += r1.x; v1.y += r1.y;
                }
                *(float2*)(Cf + o0) = v0;
                *(float2*)(Cf + o1) = v1;
            }
        }
    }
    #undef ISSUE
}

// ---------------- tensor-core flash attention --------------------------------
// grid (S/128, H, B), 256 threads (8 warps x 16 query rows).
// Q pre-scaled by log2e (bf16 hi/lo). K bf16 hi/lo. V fp16 hi/lo.
// 3-stage KV ring; exp via ex2.approx.f16x2; P frags = exp output;
// l via MMA against ones. MMAs grouped by term for accumulator independence.
#define AQ_HI 0u
#define AQ_LO 16384u
#define AKV0  32768u
#define AKV_STG 32768u
#define A_SMEM (32768u + 3u*32768u)

__global__ __launch_bounds__(256) void attn_mma_kernel(
    const __nv_bfloat16* __restrict__ Qhi, const __nv_bfloat16* __restrict__ Qlo,
    const __nv_bfloat16* __restrict__ Khi, const __nv_bfloat16* __restrict__ Klo,
    const __half* __restrict__ Vhi, const __half* __restrict__ Vlo,
    const float* __restrict__ bias,
    __nv_bfloat16* __restrict__ chi, __nv_bfloat16* __restrict__ clo)
{
    extern __shared__ char smem[];
    uint32_t sb = smem_to_u32(smem);
    int tid = threadIdx.x, wid = tid >> 5, lane = tid & 31;
    int qt = blockIdx.x, h = blockIdx.y, b = blockIdx.z;

    // ---- Q load ----
    {
        int r = tid >> 1;
        int cb = (tid & 1) * 4;
        size_t grow = ((size_t)(b * SS + qt * 128 + r)) * DD + h * HD;
        #pragma unroll
        for (int i = 0; i < 4; i++) {
            int c16 = cb + i;
            uint32_t so = TSWZ(r, c16);
            cpasync16(sb + AQ_HI + so, Qhi + grow + c16 * 8);
            cpasync16(sb + AQ_LO + so, Qlo + grow + c16 * 8);
        }
        cpasync_commit();
    }
    // ---- KV tile issue ----
    int kvr = tid & 63;
    int kvcb = (tid >> 6) * 2;
    #define ISSUE_KV(kt, stg) do {                                              \
        uint32_t _bse = sb + AKV0 + (uint32_t)(stg) * AKV_STG;                  \
        size_t _gr = ((size_t)(b * SS + (kt) * 64 + kvr)) * DD + h * HD;        \
        _Pragma("unroll")                                                       \
        for (int _i = 0; _i < 2; _i++) {                                        \
            int _c = kvcb + _i;                                                 \
            uint32_t _so = TSWZ(kvr, _c);                                       \
            cpasync16(_bse + _so,          Khi + _gr + _c * 8);                 \
            cpasync16(_bse + 8192 + _so,   Klo + _gr + _c * 8);                 \
            cpasync16(_bse + 16384 + _so,  Vhi + _gr + _c * 8);                 \
            cpasync16(_bse + 24576 + _so,  Vlo + _gr + _c * 8);                 \
        }                                                                       \
        cpasync_commit();                                                       \
    } while (0)

    ISSUE_KV(0, 0);
    ISSUE_KV(1, 1);

    float oacc[8][4];
    #pragma unroll
    for (int na = 0; na < 8; na++)
        #pragma unroll
        for (int j = 0; j < 4; j++) oacc[na][j] = 0.f;
    float lacc[4] = {0.f, 0.f, 0.f, 0.f};
    float m0 = -1e30f, m1 = -1e30f;
    const uint32_t bones[2] = {0x3C003C00u, 0x3C003C00u};

    int arow = wid * 16 + (lane & 15);
    int ac16 = lane >> 4;
    int bro  = (lane & 7) + ((lane >> 4) & 1) * 8;
    int bc16 = (lane >> 3) & 1;
    int vro  = lane & 15;
    int vch  = lane >> 4;

    size_t brow0 = ((size_t)(b * HH + h) * SS + (qt * 128 + wid * 16 + (lane >> 2))) * SS
                   + 2 * (lane & 3);
    size_t brow1 = brow0 + 8 * (size_t)SS;

    int stg = 0;
    #pragma unroll 1
    for (int kt = 0; kt < 16; kt++) {
        cpasync_wait1();
        __syncthreads();
        if (kt + 2 < 16) {
            int ns = stg + 2; if (ns >= 3) ns -= 3;
            ISSUE_KV(kt + 2, ns);
        }
        uint32_t kvb = sb + AKV0 + (uint32_t)stg * AKV_STG;

        // ---- S = Q K^T (split 3 terms, grouped) ----
        float sacc[8][4];
        #pragma unroll
        for (int na = 0; na < 8; na++)
            #pragma unroll
            for (int j = 0; j < 4; j++) sacc[na][j] = 0.f;
        #pragma unroll
        for (int kk = 0; kk < 4; kk++) {
            uint32_t ah[4], al[4];
            uint32_t ad = sb + AQ_HI + TSWZ(arow, ac16 + kk * 2);
            ldsm4(ah, ad);
            ldsm4(al, ad + AQ_LO);
            uint32_t kh[4][4], kl[4][4];
            #pragma unroll
            for (int ng = 0; ng < 4; ng++) {
                uint32_t bd = kvb + TSWZ(bro + ng * 16, bc16 + kk * 2);
                ldsm4(kh[ng], bd);
                ldsm4(kl[ng], bd + 8192);
            }
            #pragma unroll
            for (int ng = 0; ng < 4; ng++) {
                mma16816(sacc[ng*2],   ah, kh[ng]);
                mma16816(sacc[ng*2+1], ah, kh[ng] + 2);
            }
            #pragma unroll
            for (int ng = 0; ng < 4; ng++) {
                mma16816(sacc[ng*2],   ah, kl[ng]);
                mma16816(sacc[ng*2+1], ah, kl[ng] + 2);
            }
            #pragma unroll
            for (int ng = 0; ng < 4; ng++) {
                mma16816(sacc[ng*2],   al, kh[ng]);
                mma16816(sacc[ng*2+1], al, kh[ng] + 2);
            }
        }

        // ---- bias (x log2e) + max ----
        const float* bp0 = bias + brow0 + kt * 64;
        const float* bp1 = bias + brow1 + kt * 64;
        float tm0 = -1e30f, tm1 = -1e30f;
        #pragma unroll
        for (int na = 0; na < 8; na++) {
            float2 bv0 = *(const float2*)(bp0 + na * 8);
            float2 bv1 = *(const float2*)(bp1 + na * 8);
            sacc[na][0] = fmaf(bv0.x, L2E, sacc[na][0]);
            sacc[na][1] = fmaf(bv0.y, L2E, sacc[na][1]);
            sacc[na][2] = fmaf(bv1.x, L2E, sacc[na][2]);
            sacc[na][3] = fmaf(bv1.y, L2E, sacc[na][3]);
            tm0 = fmaxf(tm0, fmaxf(sacc[na][0], sacc[na][1]));
            tm1 = fmaxf(tm1, fmaxf(sacc[na][2], sacc[na][3]));
        }
        tm0 = fmaxf(tm0, __shfl_xor_sync(0xffffffffu, tm0, 1));
        tm0 = fmaxf(tm0, __shfl_xor_sync(0xffffffffu, tm0, 2));
        tm1 = fmaxf(tm1, __shfl_xor_sync(0xffffffffu, tm1, 1));
        tm1 = fmaxf(tm1, __shfl_xor_sync(0xffffffffu, tm1, 2));
        float mn0 = fmaxf(m0, tm0), mn1 = fmaxf(m1, tm1);

        if (mn0 != m0 || mn1 != m1) {
            float c0 = ex2f(m0 - mn0), c1 = ex2f(m1 - mn1);
            #pragma unroll
            for (int na = 0; na < 8; na++) {
                oacc[na][0] *= c0; oacc[na][1] *= c0;
                oacc[na][2] *= c1; oacc[na][3] *= c1;
            }
            lacc[0] *= c0; lacc[2] *= c1;
            m0 = mn0; m1 = mn1;
        }

        // ---- p = 2^(t - m); results are P fp16 A-fragments ----
        uint32_t pf[4][4];
        #pragma unroll
        for (int kk = 0; kk < 4; kk++) {
            int n0 = 2 * kk, n1 = 2 * kk + 1;
            pf[kk][0] = ex2h2(packh(sacc[n0][0] - mn0, sacc[n0][1] - mn0));
            pf[kk][1] = ex2h2(packh(sacc[n0][2] - mn1, sacc[n0][3] - mn1));
            pf[kk][2] = ex2h2(packh(sacc[n1][0] - mn0, sacc[n1][1] - mn0));
            pf[kk][3] = ex2h2(packh(sacc[n1][2] - mn1, sacc[n1][3] - mn1));
        }

        // ---- l += row-sums of P ----
        #pragma unroll
        for (int kk = 0; kk < 4; kk++)
            mma16816h(lacc, pf[kk], bones);

        // ---- O += P V (grouped by term) ----
        #pragma unroll
        for (int kk = 0; kk < 4; kk++) {
            uint32_t vh[4][4], vl[4][4];
            #pragma unroll
            for (int j = 0; j < 4; j++) {
                uint32_t vd = kvb + 16384 + TSWZ(kk * 16 + vro, 2 * j + vch);
                ldsm4t(vh[j], vd);
                ldsm4t(vl[j], vd + 8192);
            }
            #pragma unroll
            for (int j = 0; j < 4; j++) {
                mma16816h(oacc[j*2],   pf[kk], vh[j]);
                mma16816h(oacc[j*2+1], pf[kk], vh[j] + 2);
            }
            #pragma unroll
            for (int j = 0; j < 4; j++) {
                mma16816h(oacc[j*2],   pf[kk], vl[j]);
                mma16816h(oacc[j*2+1], pf[kk], vl[j] + 2);
            }
        }
        if (++stg >= 3) stg = 0;
    }

    // ---- epilogue: ctx = O / l, write hi/lo ----
    float il0 = 1.0f / lacc[0], il1 = 1.0f / lacc[2];
    int row0 = b * SS + qt * 128 + wid * 16 + (lane >> 2);
    int colb = h * HD + 2 * (lane & 3);
    #pragma unroll
    for (int na = 0; na < 8; na++) {
        size_t o0 = (size_t)row0 * DD + colb + na * 8;
        size_t o1 = o0 + 8 * (size_t)DD;
        __nv_bfloat16 hh[2], ll[2];
        split_bf16(oacc[na][0] * il0, hh[0], ll[0]);
        split_bf16(oacc[na][1] * il0, hh[1], ll[1]);
        *(uint32_t*)(chi + o0) = *(uint32_t*)hh;
        *(uint32_t*)(clo + o0) = *(uint32_t*)ll;
        split_bf16(oacc[na][2] * il1, hh[0], ll[0]);
        split_bf16(oacc[na][3] * il1, hh[1], ll[1]);
        *(uint32_t*)(chi + o1) = *(uint32_t*)hh;
        *(uint32_t*)(clo + o1) = *(uint32_t*)ll;
    }
    #undef ISSUE_KV
}

// ---------------- launch -----------------------------------------------------
extern "C" void kernel_launch(void* const* d_in, const int* in_sizes, int n_in,
                              void* d_out, int out_size)
{
    const float* Wk   = (const float*)d_in[0];
    const float* Wo   = (const float*)d_in[1];
    const float* Wq   = (const float*)d_in[2];
    const float* Wv   = (const float*)d_in[3];
    const float* ln1  = (const float*)d_in[4];
    const float* W1   = (const float*)d_in[5];
    const float* W2   = (const float*)d_in[6];
    const float* ln2  = (const float*)d_in[7];
    const float* x    = (const float*)d_in[8];
    const float* bias = (const float*)d_in[9];
    float* out = (float*)d_out;

    #define SYM(p, s) void* p; cudaGetSymbolAddress(&p, s)
    SYM(hhi, g_hhi);  SYM(hlo, g_hlo);
    SYM(qhi, g_qhi);  SYM(qlo, g_qlo);
    SYM(khi, g_khi);  SYM(klo, g_klo);
    SYM(vhi, g_vhi);  SYM(vlo, g_vlo);
    SYM(chi, g_chi);  SYM(clo, g_clo);
    SYM(px2, g_x2);
    SYM(h2hi, g_h2hi); SYM(h2lo, g_h2lo);
    SYM(fhi, g_fhi);  SYM(flo, g_flo);
    SYM(wqh, g_wqhi); SYM(wql, g_wqlo);
    SYM(wkh, g_wkhi); SYM(wkl, g_wklo);
    SYM(wvh, g_wvhi); SYM(wvl, g_wvlo);
    SYM(woh, g_wohi); SYM(wol, g_wolo);
    SYM(w1h, g_w1hi); SYM(w1l, g_w1lo);
    SYM(w2h, g_w2hi); SYM(w2l, g_w2lo);
    #undef SYM

    static bool attr_set = false;
    if (!attr_set) {
        cudaFuncSetAttribute(gemm_mma_kernel<1>, cudaFuncAttributeMaxDynamicSharedMemorySize, 3*STG);
        cudaFuncSetAttribute(gemm_mma_kernel<2>, cudaFuncAttributeMaxDynamicSharedMemorySize, 3*STG);
        cudaFuncSetAttribute(gemm_mma_kernel<3>, cudaFuncAttributeMaxDynamicSharedMemorySize, 3*STG);
        cudaFuncSetAttribute(gemm_mma_kernel<4>, cudaFuncAttributeMaxDynamicSharedMemorySize, 3*STG);
        cudaFuncSetAttribute(gemm_mma_kernel<5>, cudaFuncAttributeMaxDynamicSharedMemorySize, 3*STG);
        cudaFuncSetAttribute(attn_mma_kernel, cudaFuncAttributeMaxDynamicSharedMemorySize, A_SMEM);
        attr_set = true;
    }

    typedef const __nv_bfloat16* cbf;
    typedef __nv_bfloat16* bf;

    // fused weight conversions (one launch)
    CvtArgs ca;
    ca.s[0] = Wq; ca.h[0] = (bf)wqh; ca.l[0] = (bf)wql; ca.n4[0] = DD*DD/4;
    ca.s[1] = Wk; ca.h[1] = (bf)wkh; ca.l[1] = (bf)wkl; ca.n4[1] = DD*DD/4;
    ca.s[2] = Wv; ca.h[2] = (bf)wvh; ca.l[2] = (bf)wvl; ca.n4[2] = DD*DD/4;
    ca.s[3] = Wo; ca.h[3] = (bf)woh; ca.l[3] = (bf)wol; ca.n4[3] = DD*DD/4;
    ca.s[4] = W1; ca.h[4] = (bf)w1h; ca.l[4] = (bf)w1l; ca.n4[4] = FF*DD/4;
    ca.s[5] = W2; ca.h[5] = (bf)w2h; ca.l[5] = (bf)w2l; ca.n4[5] = DD*FF/4;
    dim3 gc(FF*DD/4/256, 6);
    cvt6_kernel<<<gc, 256>>>(ca);

    // 1. h = rmsnorm(x, ln1) -> hi/lo
    rmsnorm_kernel<<<NROWS, 256>>>(x, ln1, (bf)hhi, (bf)hlo);

    // 2-4. q/k/v = h @ W^T
    dim3 gD(DD/128, NROWS/128);
    gemm_mma_kernel<5><<<gD, 256, 3*STG>>>((cbf)hhi, (cbf)hlo, (cbf)wqh, (cbf)wql,
                                           nullptr, nullptr, (bf)qhi, (bf)qlo, DD, DD);
    gemm_mma_kernel<3><<<gD, 256, 3*STG>>>((cbf)hhi, (cbf)hlo, (cbf)wkh, (cbf)wkl,
                                           nullptr, nullptr, (bf)khi, (bf)klo, DD, DD);
    gemm_mma_kernel<4><<<gD, 256, 3*STG>>>((cbf)hhi, (cbf)hlo, (cbf)wvh, (cbf)wvl,
                                           nullptr, nullptr, (bf)vhi, (bf)vlo, DD, DD);

    // 5. attention -> ctx hi/lo
    dim3 ga(SS/128, HH, BB);
    attn_mma_kernel<<<ga, 256, A_SMEM>>>((cbf)qhi, (cbf)qlo, (cbf)khi, (cbf)klo,
                                         (const __half*)vhi, (const __half*)vlo,
                                         bias, (bf)chi, (bf)clo);

    // 6. x2 = x + ctx @ Wo^T (fp32)
    gemm_mma_kernel<2><<<gD, 256, 3*STG>>>((cbf)chi, (cbf)clo, (cbf)woh, (cbf)wol,
                                           x, (float*)px2, nullptr, nullptr, DD, DD);

    // 7. h2 = rmsnorm(x2, ln2) -> hi/lo
    rmsnorm_kernel<<<NROWS, 256>>>((const float*)px2, ln2, (bf)h2hi, (bf)h2lo);

    // 8. ff = relu(h2 @ W1^T) -> hi/lo
    dim3 gF(FF/128, NROWS/128);
    gemm_mma_kernel<1><<<gF, 256, 3*STG>>>((cbf)h2hi, (cbf)h2lo, (cbf)w1h, (cbf)w1l,
                                           nullptr, nullptr, (bf)fhi, (bf)flo, FF, DD);

    // 9. out = x2 + ff @ W2^T (fp32)
    gemm_mma_kernel<2><<<gD, 256, 3*STG>>>((cbf)fhi, (cbf)flo, (cbf)w2h, (cbf)w2l,
                                           (const float*)px2, out, nullptr, nullptr, DD, FF);
}